// round 7
// baseline (speedup 1.0000x reference)
#include <cuda_runtime.h>
#include <cuda_bf16.h>

#define FULLM 0xFFFFFFFFu

constexpr int B_ = 8;
constexpr int N_ = 2048;
constexpr int K_ = 32;
constexpr int CO_ = 64;
constexpr int ROWS_ = B_ * N_;   // 16384
constexpr int CAP_ = 512;

// ---------------- static scratch (no allocation) ----------------
__device__ float d_sq[ROWS_];
__device__ float d_xt[64 * ROWS_];     // transposed features [c][global row]
__device__ int   d_idx[ROWS_ * K_];
__device__ float d_h [ROWS_ * CO_];
__device__ float d_mx[ROWS_ * CO_];
__device__ float d_mn[ROWS_ * CO_];
__device__ float d_sum[CO_];
__device__ float d_ssq[CO_];
__device__ float d_scale[CO_];
__device__ float d_shift[CO_];
__device__ float d_wd2[64 * 64];
__device__ float d_wf2[64 * 64];

// ---------------- packed fp32x2 helpers ----------------
__device__ __forceinline__ unsigned long long pk2(float v) {
    unsigned long long r;
    asm("mov.b64 %0, {%1, %1};" : "=l"(r) : "f"(v));
    return r;
}
__device__ __forceinline__ void fma2(unsigned long long& d, unsigned long long a, unsigned long long b) {
    asm("fma.rn.f32x2 %0, %1, %2, %0;" : "+l"(d) : "l"(a), "l"(b));
}
__device__ __forceinline__ float2 up2(unsigned long long v) {
    float2 r;
    asm("mov.b64 {%0, %1}, %2;" : "=f"(r.x), "=f"(r.y) : "l"(v));
    return r;
}
__device__ __forceinline__ unsigned f2u(float f) {
    unsigned u = __float_as_uint(f);
    return u ^ ((unsigned)((int)u >> 31) | 0x80000000u);
}

// ---------------- warp argmax on u64 keys ----------------
__device__ __forceinline__ void warp_argmax64(unsigned long long v, int l,
                                              unsigned long long& mv, int& ml) {
    unsigned long long bv = v; int bl = l;
#pragma unroll
    for (int off = 16; off > 0; off >>= 1) {
        unsigned long long ov = __shfl_down_sync(FULLM, bv, off);
        int                ol = __shfl_down_sync(FULLM, bl, off);
        if (ov > bv) { bv = ov; bl = ol; }
    }
    mv = __shfl_sync(FULLM, bv, 0);
    ml = __shfl_sync(FULLM, bl, 0);
}

__device__ __forceinline__ void insert64(unsigned long long cand,
                                         unsigned long long& cur,
                                         unsigned long long& cmax, int& cml, int l) {
    unsigned m = __ballot_sync(FULLM, cand < cmax);
    while (m) {
        int s = __ffs(m) - 1;
        unsigned long long cn = __shfl_sync(FULLM, cand, s);
        if (l == cml) cur = cn;
        warp_argmax64(cur, l, cmax, cml);
        m &= ~(1u << s);
        m &= __ballot_sync(FULLM, cand < cmax);
    }
}

// ---------------- transposes ----------------
__global__ void xpose3_kernel(const float* __restrict__ a) {
    int t = blockIdx.x * 256 + threadIdx.x;   // 3*16384 elems
    if (t < 3 * ROWS_) {
        int c = t >> 14, i = t & (ROWS_ - 1);
        d_xt[t] = a[i * 3 + c];
    }
}

__global__ void xpose64_kernel() {
    __shared__ float t[64][65];
    const int tid = threadIdx.x;
    const int i0  = blockIdx.x * 64;
#pragma unroll
    for (int k = 0; k < 4; k++) {
        int L = tid + 256 * k;
        int r = L >> 4, c4 = L & 15;
        float4 f = *reinterpret_cast<const float4*>(&d_h[(size_t)(i0 + r) * 64 + 4 * c4]);
        t[4*c4+0][r] = f.x; t[4*c4+1][r] = f.y;
        t[4*c4+2][r] = f.z; t[4*c4+3][r] = f.w;
    }
    __syncthreads();
#pragma unroll
    for (int k = 0; k < 4; k++) {
        int Wv = tid + 256 * k;
        int c = Wv >> 4, r4 = Wv & 15;
        float4 f = make_float4(t[c][4*r4], t[c][4*r4+1], t[c][4*r4+2], t[c][4*r4+3]);
        *reinterpret_cast<float4*>(&d_xt[(size_t)c * ROWS_ + i0 + 4 * r4]) = f;
    }
}

// ---------------- squared norms ----------------
template<int C>
__global__ void sqnorm_kernel(const float* __restrict__ xin) {
    const float* x = xin ? xin : (const float*)d_h;
    int i = blockIdx.x * blockDim.x + threadIdx.x;
    if (i >= ROWS_) return;
    const float* p = x + (size_t)i * C;
    float s = 0.f;
    if (C == 3) {
        s = p[0]*p[0] + p[1]*p[1] + p[2]*p[2];
    } else {
#pragma unroll
        for (int c4 = 0; c4 < C / 4; c4++) {
            float4 f = reinterpret_cast<const float4*>(p)[c4];
            s += f.x*f.x + f.y*f.y + f.z*f.z + f.w*f.w;
        }
    }
    d_sq[i] = s;
}

// ---------------- fused kNN: 16 rows/block, dist row in smem, in-block select ----------------
// dynamic smem layout (bytes):
//   [0, 131072)                      dist: u32[16][2048]
//   [131072, +C*64)                  AT:   float[C][16]
//   [.., +C*264*4)                   BT:   float[C][264]  (tile of 256 cols, padded)
//   [.., +64) sqa[16]  [.., +1024) sqb[256]
//   buf (8 warps x CAP u64): overlays BT when C==64 (BT >= 32KB), separate when C==3
template<int C>
struct FK {
    static constexpr int OFF_AT  = 131072;
    static constexpr int OFF_BT  = OFF_AT + C * 64;
    static constexpr int OFF_SQA = OFF_BT + C * 264 * 4;
    static constexpr int OFF_SQB = OFF_SQA + 64;
    static constexpr int OFF_END = OFF_SQB + 1024;
    static constexpr int OFF_BUF = (C == 64) ? OFF_BT : OFF_END;
    static constexpr int TOTAL   = (C == 64) ? OFF_END : OFF_END + 8 * CAP_ * 8;
};

__device__ __forceinline__ void knn_fallback_smem(const unsigned* dr, int grow, int l) {
    unsigned long long cur = ((unsigned long long)dr[l] << 32) | (unsigned)l;
    unsigned long long cmax; int cml;
    warp_argmax64(cur, l, cmax, cml);
    for (int ch = 1; ch < 64; ch++) {
        int col = ch * 32 + l;
        unsigned long long cand = ((unsigned long long)dr[col] << 32) | (unsigned)col;
        insert64(cand, cur, cmax, cml, l);
    }
    d_idx[grow * K_ + l] = (int)(unsigned)cur;
}

template<int C>
__global__ void __launch_bounds__(256, 1) fknn_kernel() {
    extern __shared__ __align__(16) unsigned char sm[];
    unsigned* distm = reinterpret_cast<unsigned*>(sm);
    float*    AT    = reinterpret_cast<float*>(sm + FK<C>::OFF_AT);    // [C][16]
    float*    BT    = reinterpret_cast<float*>(sm + FK<C>::OFF_BT);    // [C][264]
    float*    sqa   = reinterpret_cast<float*>(sm + FK<C>::OFF_SQA);
    float*    sqb   = reinterpret_cast<float*>(sm + FK<C>::OFF_SQB);

    const int tid = threadIdx.x, w = tid >> 5, l = tid & 31;
    const int row0 = blockIdx.x * 16;        // 16 | 2048, never straddles batch
    const int b    = row0 >> 11;
    const size_t cb = (size_t)b * N_;

    // A tile + sqa
    {
        constexpr int NA = C * 4;            // float4 count
        if (tid < NA) {
            int c = tid >> 2, r4 = tid & 3;
            float4 f = *reinterpret_cast<const float4*>(&d_xt[(size_t)c * ROWS_ + row0 + 4 * r4]);
            float* at = AT + c * 16 + 4 * r4;
            at[0] = f.x; at[1] = f.y; at[2] = f.z; at[3] = f.w;
        }
        if (tid < 16) sqa[tid] = d_sq[row0 + tid];
    }

    const int r0 = 2 * w, r1 = 2 * w + 1;    // rows owned by this warp

    for (int tile = 0; tile < 8; tile++) {
        const int col0 = tile * 256;
        __syncthreads();
        // B tile: [C][256] from xT, coalesced
        for (int v = tid; v < C * 64; v += 256) {
            int c = v >> 6, p4 = v & 63;
            float4 f = *reinterpret_cast<const float4*>(&d_xt[(size_t)c * ROWS_ + cb + col0 + 4 * p4]);
            *reinterpret_cast<float4*>(&BT[c * 264 + 4 * p4]) = f;
        }
        sqb[tid] = d_sq[cb + col0 + tid];
        __syncthreads();

        // GEMM: rows (r0, r1) x cols 8l..8l+7 (col pairs packed)
        unsigned long long acc[2][4];
#pragma unroll
        for (int j = 0; j < 4; j++) { acc[0][j] = 0ull; acc[1][j] = 0ull; }
#pragma unroll 16
        for (int c = 0; c < C; c++) {
            float2 av = *reinterpret_cast<const float2*>(&AT[c * 16 + r0]);
            unsigned long long pa0 = pk2(av.x), pa1 = pk2(av.y);
            ulonglong2 b01 = *reinterpret_cast<const ulonglong2*>(&BT[c * 264 + 8 * l]);
            ulonglong2 b23 = *reinterpret_cast<const ulonglong2*>(&BT[c * 264 + 8 * l + 4]);
            fma2(acc[0][0], pa0, b01.x); fma2(acc[0][1], pa0, b01.y);
            fma2(acc[0][2], pa0, b23.x); fma2(acc[0][3], pa0, b23.y);
            fma2(acc[1][0], pa1, b01.x); fma2(acc[1][1], pa1, b01.y);
            fma2(acc[1][2], pa1, b23.x); fma2(acc[1][3], pa1, b23.y);
        }

        float sa0 = sqa[r0], sa1 = sqa[r1];
        uint4 o0a, o0b, o1a, o1b;
        {
            float2 d0 = up2(acc[0][0]), d1 = up2(acc[0][1]), d2 = up2(acc[0][2]), d3 = up2(acc[0][3]);
            o0a.x = f2u(sa0 + sqb[8*l+0] - 2.f*d0.x); o0a.y = f2u(sa0 + sqb[8*l+1] - 2.f*d0.y);
            o0a.z = f2u(sa0 + sqb[8*l+2] - 2.f*d1.x); o0a.w = f2u(sa0 + sqb[8*l+3] - 2.f*d1.y);
            o0b.x = f2u(sa0 + sqb[8*l+4] - 2.f*d2.x); o0b.y = f2u(sa0 + sqb[8*l+5] - 2.f*d2.y);
            o0b.z = f2u(sa0 + sqb[8*l+6] - 2.f*d3.x); o0b.w = f2u(sa0 + sqb[8*l+7] - 2.f*d3.y);
        }
        {
            float2 d0 = up2(acc[1][0]), d1 = up2(acc[1][1]), d2 = up2(acc[1][2]), d3 = up2(acc[1][3]);
            o1a.x = f2u(sa1 + sqb[8*l+0] - 2.f*d0.x); o1a.y = f2u(sa1 + sqb[8*l+1] - 2.f*d0.y);
            o1a.z = f2u(sa1 + sqb[8*l+2] - 2.f*d1.x); o1a.w = f2u(sa1 + sqb[8*l+3] - 2.f*d1.y);
            o1b.x = f2u(sa1 + sqb[8*l+4] - 2.f*d2.x); o1b.y = f2u(sa1 + sqb[8*l+5] - 2.f*d2.y);
            o1b.z = f2u(sa1 + sqb[8*l+6] - 2.f*d3.x); o1b.w = f2u(sa1 + sqb[8*l+7] - 2.f*d3.y);
        }
        *reinterpret_cast<uint4*>(&distm[r0 * 2048 + col0 + 8 * l])     = o0a;
        *reinterpret_cast<uint4*>(&distm[r0 * 2048 + col0 + 8 * l + 4]) = o0b;
        *reinterpret_cast<uint4*>(&distm[r1 * 2048 + col0 + 8 * l])     = o1a;
        *reinterpret_cast<uint4*>(&distm[r1 * 2048 + col0 + 8 * l + 4]) = o1b;
    }
    __syncthreads();

    // ---- selection: this warp handles rows r0, r1 ----
    unsigned long long* bufw =
        reinterpret_cast<unsigned long long*>(sm + FK<C>::OFF_BUF) + (size_t)w * CAP_;

#pragma unroll
    for (int rr = 0; rr < 2; rr++) {
        const int r = 2 * w + rr;
        const unsigned* dr = distm + r * 2048;

        // sweep 1: per-lane min over its 64 cols (16 x uint4)
        unsigned lmin = 0xFFFFFFFFu;
#pragma unroll 4
        for (int j = 0; j < 16; j++) {
            uint4 v = *reinterpret_cast<const uint4*>(dr + 4 * l + 128 * j);
            lmin = min(lmin, min(min(v.x, v.y), min(v.z, v.w)));
        }
        unsigned tau = __reduce_max_sync(FULLM, lmin);   // >= true 32nd distance

        // sweep 2: ballot-compact survivors into bufw as (dist<<32)|col
        int cnt = 0;
        for (int j = 0; j < 16; j++) {
            uint4 v = *reinterpret_cast<const uint4*>(dr + 4 * l + 128 * j);
            unsigned e[4] = {v.x, v.y, v.z, v.w};
#pragma unroll
            for (int q = 0; q < 4; q++) {
                bool p = e[q] <= tau;
                unsigned m = __ballot_sync(FULLM, p);
                if (p) {
                    int pos = cnt + __popc(m & ((1u << l) - 1u));
                    if (pos < CAP_)
                        bufw[pos] = ((unsigned long long)e[q] << 32) | (unsigned)(4 * l + 128 * j + q);
                }
                cnt += __popc(m);
            }
        }

        if (cnt > CAP_) { knn_fallback_smem(dr, row0 + r, l); continue; }

        unsigned long long cur = bufw[l];                // cnt >= 32 guaranteed
        unsigned long long cmax; int cml;
        warp_argmax64(cur, l, cmax, cml);
        for (int base = 32; base < cnt; base += 32) {
            int ix = base + l;
            unsigned long long cand = (ix < cnt) ? bufw[ix] : ~0ull;
            insert64(cand, cur, cmax, cml, l);
        }
        d_idx[(row0 + r) * K_ + l] = (int)(unsigned)cur;
    }
}

// ---------------- stats helpers ----------------
__global__ void zero_stats_kernel() {
    int t = threadIdx.x;
    if (t < CO_) { d_sum[t] = 0.f; d_ssq[t] = 0.f; }
}

__global__ void finalize_kernel(const float* __restrict__ gamma, const float* __restrict__ beta) {
    int o = threadIdx.x;
    if (o < CO_) {
        float cnt  = (float)(B_ * N_ * K_);
        float mean = d_sum[o] / cnt;
        float var  = d_ssq[o] / cnt - mean * mean;
        float sc   = gamma[o] * rsqrtf(var + 1e-5f);
        d_scale[o] = sc;
        d_shift[o] = beta[o] - mean * sc;
    }
}

__global__ void prep_kernel(const float* __restrict__ W2) {
    int t = blockIdx.x * 256 + threadIdx.x;
    if (t < 4096) {
        int c = t >> 6, o = t & 63;
        float wd = W2[o * 128 + c];
        d_wd2[t] = wd;
        d_wf2[t] = W2[o * 128 + 64 + c] - wd;
    }
}

// ---------------- conv stage 1 (CIN=3): warp per point ----------------
__global__ void __launch_bounds__(256) conv3_kernel(const float* __restrict__ a,
                                                    const float* __restrict__ W) {
    __shared__ float snb[8][3][33];
    __shared__ float cs[64], css[64];
    const int tid = threadIdx.x, w = tid >> 5, l = tid & 31;
    const int pt = blockIdx.x * 8 + w;
    const int b  = pt >> 11, n = pt & (N_ - 1);
    const size_t pbase = (size_t)b * N_;

    if (tid < 64) { cs[tid] = 0.f; css[tid] = 0.f; }

    int nb = d_idx[(pbase + n) * K_ + l];
    const float* xp = a + (pbase + nb) * 3;
    snb[w][0][l] = xp[0]; snb[w][1][l] = xp[1]; snb[w][2][l] = xp[2];

    const float* cp = a + (pbase + n) * 3;
    float cx = cp[0], cy = cp[1], cz = cp[2];

    float wd[2][3], bse[2];
#pragma unroll
    for (int h = 0; h < 2; h++) {
        const float* wr = W + (2 * l + h) * 6;
        wd[h][0] = wr[0]; wd[h][1] = wr[1]; wd[h][2] = wr[2];
        bse[h] = cx * (wr[3] - wr[0]) + cy * (wr[4] - wr[1]) + cz * (wr[5] - wr[2]);
    }
    __syncwarp();
    __syncthreads();

    float s0 = 0.f, ss0 = 0.f, mx0 = -3.4e38f, mn0 = 3.4e38f;
    float s1 = 0.f, ss1 = 0.f, mx1 = -3.4e38f, mn1 = 3.4e38f;
#pragma unroll 8
    for (int r = 0; r < 32; r++) {
        float nx = snb[w][0][r], ny = snb[w][1][r], nz = snb[w][2][r];
        float y0 = fmaf(nz, wd[0][2], fmaf(ny, wd[0][1], nx * wd[0][0])) + bse[0];
        float y1 = fmaf(nz, wd[1][2], fmaf(ny, wd[1][1], nx * wd[1][0])) + bse[1];
        s0 += y0; ss0 = fmaf(y0, y0, ss0); mx0 = fmaxf(mx0, y0); mn0 = fminf(mn0, y0);
        s1 += y1; ss1 = fmaf(y1, y1, ss1); mx1 = fmaxf(mx1, y1); mn1 = fminf(mn1, y1);
    }
    size_t gi = (pbase + n) * 64 + 2 * l;
    d_mx[gi] = mx0; d_mx[gi + 1] = mx1;
    d_mn[gi] = mn0; d_mn[gi + 1] = mn1;

    atomicAdd(&cs [2 * l], s0);  atomicAdd(&cs [2 * l + 1], s1);
    atomicAdd(&css[2 * l], ss0); atomicAdd(&css[2 * l + 1], ss1);
    __syncthreads();
    if (tid < 64) {
        atomicAdd(&d_sum[tid], cs[tid]);
        atomicAdd(&d_ssq[tid], css[tid]);
    }
}

// ---------------- conv stage 2 (CIN=64): 8 points/block, 8x8 thread tile ----------------
constexpr int CP_ = 264;

__global__ void __launch_bounds__(256) conv64_kernel() {
    __shared__ __align__(16) float bufT[64][CP_];
    __shared__ __align__(16) float swd[64][68];
    __shared__ __align__(16) float swf[64][68];
    __shared__ float cen[8][64];
    __shared__ float bs[8][64];
    __shared__ int   sidx[256];
    __shared__ float cs[64], css[64];

    const float* x = (const float*)d_h;
    const int tid = threadIdx.x;
    const int pid = blockIdx.x;
    const int b   = pid >> 8;
    const int n0  = (pid & 255) * 8;
    const size_t base = (size_t)b * N_;

    if (tid < 64) { cs[tid] = 0.f; css[tid] = 0.f; }
    sidx[tid] = d_idx[(base + n0 + (tid >> 5)) * K_ + (tid & 31)];
    for (int v = tid; v < 4096; v += 256) {
        int c = v >> 6, o = v & 63;
        swd[c][o] = d_wd2[v];
        swf[c][o] = d_wf2[v];
    }
    for (int v = tid; v < 512; v += 256) {
        int p = v >> 6, c = v & 63;
        cen[p][c] = x[(base + n0 + p) * 64 + c];
    }
    __syncthreads();

    for (int v = tid; v < 4096; v += 256) {
        int c4 = v >> 8, r = v & 255;
        float4 f = *reinterpret_cast<const float4*>(x + (base + sidx[r]) * 64 + 4 * c4);
        bufT[4*c4+0][r] = f.x; bufT[4*c4+1][r] = f.y;
        bufT[4*c4+2][r] = f.z; bufT[4*c4+3][r] = f.w;
    }
    for (int v = tid; v < 512; v += 256) {
        int p = v >> 6, o = v & 63;
        float t = 0.f;
#pragma unroll 8
        for (int c = 0; c < 64; c++) t = fmaf(cen[p][c], swf[c][o], t);
        bs[p][o] = t;
    }
    __syncthreads();

    const int rg = tid >> 3, g = tid & 7;
    const int r0 = rg * 8;
    unsigned long long acc[8][4];
#pragma unroll
    for (int i = 0; i < 8; i++)
#pragma unroll
        for (int j = 0; j < 4; j++) acc[i][j] = 0ull;

#pragma unroll 2
    for (int c = 0; c < 64; c++) {
        float4 a0 = *reinterpret_cast<const float4*>(&bufT[c][r0]);
        float4 a1 = *reinterpret_cast<const float4*>(&bufT[c][r0 + 4]);
        ulonglong2 w01 = *reinterpret_cast<const ulonglong2*>(&swd[c][8 * g]);
        ulonglong2 w23 = *reinterpret_cast<const ulonglong2*>(&swd[c][8 * g + 4]);
        unsigned long long pa[8] = {pk2(a0.x), pk2(a0.y), pk2(a0.z), pk2(a0.w),
                                    pk2(a1.x), pk2(a1.y), pk2(a1.z), pk2(a1.w)};
#pragma unroll
        for (int i = 0; i < 8; i++) {
            fma2(acc[i][0], pa[i], w01.x);
            fma2(acc[i][1], pa[i], w01.y);
            fma2(acc[i][2], pa[i], w23.x);
            fma2(acc[i][3], pa[i], w23.y);
        }
    }
    __syncthreads();

    float* st0 = &bufT[0][0];
    float* st1 = st0 + 2048;
    float* st2 = st0 + 4096;
    float* st3 = st0 + 6144;

#pragma unroll
    for (int cp = 0; cp < 4; cp++) {
        float s_x = 0.f, ss_x = 0.f, mx_x = -3.4e38f, mn_x = 3.4e38f;
        float s_y = 0.f, ss_y = 0.f, mx_y = -3.4e38f, mn_y = 3.4e38f;
#pragma unroll
        for (int i = 0; i < 8; i++) {
            float2 v = up2(acc[i][cp]);
            s_x += v.x; ss_x = fmaf(v.x, v.x, ss_x); mx_x = fmaxf(mx_x, v.x); mn_x = fminf(mn_x, v.x);
            s_y += v.y; ss_y = fmaf(v.y, v.y, ss_y); mx_y = fmaxf(mx_y, v.y); mn_y = fminf(mn_y, v.y);
        }
        int o0 = 8 * g + 2 * cp, o1 = o0 + 1;
        st0[rg * 64 + o0] = s_x;  st0[rg * 64 + o1] = s_y;
        st1[rg * 64 + o0] = ss_x; st1[rg * 64 + o1] = ss_y;
        st2[rg * 64 + o0] = mx_x; st2[rg * 64 + o1] = mx_y;
        st3[rg * 64 + o0] = mn_x; st3[rg * 64 + o1] = mn_y;
    }
    __syncthreads();

    for (int v = tid; v < 512; v += 256) {
        int p = v >> 6, o = v & 63;
        float S = 0.f, SS = 0.f, MX = -3.4e38f, MN = 3.4e38f;
#pragma unroll
        for (int q = 0; q < 4; q++) {
            int rr = 4 * p + q;
            S  += st0[rr * 64 + o];
            SS += st1[rr * 64 + o];
            MX  = fmaxf(MX, st2[rr * 64 + o]);
            MN  = fminf(MN, st3[rr * 64 + o]);
        }
        float bb = bs[p][o];
        size_t gi = (base + n0 + p) * 64 + o;
        d_mx[gi] = MX + bb;
        d_mn[gi] = MN + bb;
        atomicAdd(&cs[o],  S + 32.f * bb);
        atomicAdd(&css[o], SS + 2.f * bb * S + 32.f * bb * bb);
    }
    __syncthreads();
    if (tid < 64) {
        atomicAdd(&d_sum[tid], cs[tid]);
        atomicAdd(&d_ssq[tid], css[tid]);
    }
}

// ---------------- pass B ----------------
__global__ void passb_kernel(float* __restrict__ outp) {
    float* out = outp ? outp : (float*)d_h;
    int e = blockIdx.x * 256 + threadIdx.x;
    if (e >= ROWS_ * CO_) return;
    int o = e & 63;
    float sc = d_scale[o];
    float v  = (sc >= 0.f) ? d_mx[e] : d_mn[e];
    float y  = sc * v + d_shift[o];
    out[e] = (y >= 0.f) ? y : 0.2f * y;
}

// ---------------- launch ----------------
extern "C" void kernel_launch(void* const* d_in, const int* in_sizes, int n_in,
                              void* d_out, int out_size) {
    const float* a  = (const float*)d_in[0];
    const float* W1 = (const float*)d_in[2];
    const float* g1 = (const float*)d_in[3];
    const float* b1 = (const float*)d_in[4];
    const float* W2 = (const float*)d_in[5];
    const float* g2 = (const float*)d_in[6];
    const float* b2 = (const float*)d_in[7];
    float* out = (float*)d_out;

    static bool attr_set = false;
    if (!attr_set) {
        cudaFuncSetAttribute(fknn_kernel<3>,  cudaFuncAttributeMaxDynamicSharedMemorySize, FK<3>::TOTAL);
        cudaFuncSetAttribute(fknn_kernel<64>, cudaFuncAttributeMaxDynamicSharedMemorySize, FK<64>::TOTAL);
        attr_set = true;
    }

    int pts = ROWS_;

    prep_kernel<<<16, 256>>>(W2);

    // stage 1 (C = 3)
    xpose3_kernel<<<(3 * pts + 255) / 256, 256>>>(a);
    sqnorm_kernel<3><<<(pts + 255) / 256, 256>>>(a);
    fknn_kernel<3><<<pts / 16, 256, FK<3>::TOTAL>>>();
    zero_stats_kernel<<<1, 64>>>();
    conv3_kernel<<<pts / 8, 256>>>(a, W1);
    finalize_kernel<<<1, 64>>>(g1, b1);
    passb_kernel<<<(pts * CO_ + 255) / 256, 256>>>(nullptr);   // -> d_h

    // stage 2 (C = 64)
    xpose64_kernel<<<pts / 64, 256>>>();
    sqnorm_kernel<64><<<(pts + 255) / 256, 256>>>(nullptr);
    fknn_kernel<64><<<pts / 16, 256, FK<64>::TOTAL>>>();
    zero_stats_kernel<<<1, 64>>>();
    conv64_kernel<<<pts / 8, 256>>>();
    finalize_kernel<<<1, 64>>>(g2, b2);
    passb_kernel<<<(pts * CO_ + 255) / 256, 256>>>(out);       // -> d_out
}